// round 4
// baseline (speedup 1.0000x reference)
#include <cuda_runtime.h>

// Problem constants (fixed by the dataset reference)
#define SIZE    4096
#define LOG_N   12
#define NPAIRS  (SIZE / 2)          // 2048
#define N4      (SIZE / 4)          // 1024 float4 per row

// Fused kernel:
//  Phase A (per thread, once): compose the 12-layer chain of 2x2 butterfly
//    matrices for this thread's two pairs, in registers.
//    Row-vector convention: out = v @ W0 @ ... @ W11  ==>  M = W0*W1*...*W11.
//    W is only 384 KB -> L2-resident; the redundant recompute across y-blocks
//    is nearly free and removes a whole serialized kernel launch.
//  Phase B: persistent single-wave streaming pass. Each thread owns one
//    float4 column slot (2 adjacent pairs) and strides over rows with a
//    4-deep manual unroll for memory-level parallelism. Streaming cache
//    hints: every byte of x/out is touched exactly once.
__global__ __launch_bounds__(256, 8)
void butterfly_fused(const float4* __restrict__ x4, float4* __restrict__ o4,
                     const float4* __restrict__ W4, int batch) {
    const int c = blockIdx.x * blockDim.x + threadIdx.x;   // 0..N4-1

    // ---- Phase A: inline composition (fp32) ----
    float a00 = 1.f, a01 = 0.f, a10 = 0.f, a11 = 1.f;      // pair 2c
    float b00 = 1.f, b01 = 0.f, b10 = 0.f, b11 = 1.f;      // pair 2c+1
#pragma unroll
    for (int l = 0; l < LOG_N; ++l) {
        const float4 wa = __ldg(&W4[l * NPAIRS + 2 * c + 0]);
        const float4 wb = __ldg(&W4[l * NPAIRS + 2 * c + 1]);
        // M = M @ Wl ; w = (w00, w01, w10, w11)
        float t00 = fmaf(a01, wa.z, a00 * wa.x);
        float t01 = fmaf(a01, wa.w, a00 * wa.y);
        float t10 = fmaf(a11, wa.z, a10 * wa.x);
        float t11 = fmaf(a11, wa.w, a10 * wa.y);
        a00 = t00; a01 = t01; a10 = t10; a11 = t11;
        float u00 = fmaf(b01, wb.z, b00 * wb.x);
        float u01 = fmaf(b01, wb.w, b00 * wb.y);
        float u10 = fmaf(b11, wb.z, b10 * wb.x);
        float u11 = fmaf(b11, wb.w, b10 * wb.y);
        b00 = u00; b01 = u01; b10 = u10; b11 = u11;
    }

    // ---- Phase B: streaming pass, grid-stride over rows, unroll 4 ----
    const int    G     = gridDim.y;
    const size_t strd  = (size_t)G * N4;       // one grid-stride step in float4s
    int r = blockIdx.y;
    size_t base = (size_t)r * N4 + c;

    for (; r + 3 * G < batch; r += 4 * G, base += 4 * strd) {
        const size_t i0 = base;
        const size_t i1 = base + strd;
        const size_t i2 = base + 2 * strd;
        const size_t i3 = base + 3 * strd;
        const float4 v0 = __ldcs(&x4[i0]);
        const float4 v1 = __ldcs(&x4[i1]);
        const float4 v2 = __ldcs(&x4[i2]);
        const float4 v3 = __ldcs(&x4[i3]);
        float4 y0, y1, y2, y3;
        y0.x = fmaf(v0.y, a10, v0.x * a00); y0.y = fmaf(v0.y, a11, v0.x * a01);
        y0.z = fmaf(v0.w, b10, v0.z * b00); y0.w = fmaf(v0.w, b11, v0.z * b01);
        y1.x = fmaf(v1.y, a10, v1.x * a00); y1.y = fmaf(v1.y, a11, v1.x * a01);
        y1.z = fmaf(v1.w, b10, v1.z * b00); y1.w = fmaf(v1.w, b11, v1.z * b01);
        y2.x = fmaf(v2.y, a10, v2.x * a00); y2.y = fmaf(v2.y, a11, v2.x * a01);
        y2.z = fmaf(v2.w, b10, v2.z * b00); y2.w = fmaf(v2.w, b11, v2.z * b01);
        y3.x = fmaf(v3.y, a10, v3.x * a00); y3.y = fmaf(v3.y, a11, v3.x * a01);
        y3.z = fmaf(v3.w, b10, v3.z * b00); y3.w = fmaf(v3.w, b11, v3.z * b01);
        __stcs(&o4[i0], y0);
        __stcs(&o4[i1], y1);
        __stcs(&o4[i2], y2);
        __stcs(&o4[i3], y3);
    }
    for (; r < batch; r += G, base += strd) {
        const float4 v = __ldcs(&x4[base]);
        float4 y;
        y.x = fmaf(v.y, a10, v.x * a00); y.y = fmaf(v.y, a11, v.x * a01);
        y.z = fmaf(v.w, b10, v.z * b00); y.w = fmaf(v.w, b11, v.z * b01);
        __stcs(&o4[base], y);
    }
}

extern "C" void kernel_launch(void* const* d_in, const int* in_sizes, int n_in,
                              void* d_out, int out_size) {
    const float* x = (const float*)d_in[0];   // [batch, SIZE] fp32
    const float* W = (const float*)d_in[1];   // [LOG_N, NPAIRS, 2, 2] fp32
    float* out = (float*)d_out;               // [batch, SIZE] fp32

    const int batch = in_sizes[0] / SIZE;

    // Persistent single wave: 148 SMs x 8 blocks(256thr) = 1184 blocks.
    // grid.x = 4 column groups -> grid.y = 296 row-stride blocks.
    dim3 grid(N4 / 256, 296);
    butterfly_fused<<<grid, 256>>>((const float4*)x, (float4*)out,
                                   (const float4*)W, batch);
}